// round 15
// baseline (speedup 1.0000x reference)
#include <cuda_runtime.h>
#include <cuda_bf16.h>
#include <math.h>
#include <stdint.h>

#define DD 2048
#define SS 8192
#define SD (SS*DD)
#define DD2 (DD*DD)
#define INNER_LR 0.01f

// ---------------- scratch arenas ----------------
#define F_Q   ((size_t)0*SD)
#define F_K   ((size_t)1*SD)
#define F_V   ((size_t)2*SD)
#define F_H   ((size_t)3*SD)
#define F_A   ((size_t)4*SD)
#define F_DY  ((size_t)5*SD)
#define F_DH  ((size_t)6*SD)
#define F_GW1 ((size_t)7*SD)
#define F_GW2 (F_GW1 + DD2)
#define F_W1F (F_GW2 + DD2)
#define F_W2F (F_W1F + DD2)
#define F_B1F (F_W2F + DD2)
#define F_B2F (F_B1F + DD)
#define F_GB1 (F_B2F + DD)
#define F_GB2 (F_GB1 + DD)
#define F_PART (F_GB2 + DD)
#define F_ALPHA (F_PART + 2048)
#define F_TOTAL (F_ALPHA + 64)
__device__ float g_f32[F_TOTAL];

#define B_XH   ((size_t)0*SD)
#define B_XL   ((size_t)1*SD)
#define B_QH   ((size_t)2*SD)
#define B_QL   ((size_t)3*SD)
#define B_K    ((size_t)4*SD)
#define B_KT   ((size_t)5*SD)
#define B_A    ((size_t)6*SD)
#define B_AT   ((size_t)7*SD)
#define B_DY   ((size_t)8*SD)
#define B_DYT  ((size_t)9*SD)
#define B_DHT  ((size_t)10*SD)
#define B_ARH  ((size_t)11*SD)
#define B_ARL  ((size_t)12*SD)
#define B_W    ((size_t)13*SD)
#define B_WQH  (B_W + (size_t)0*DD2)
#define B_WQL  (B_W + (size_t)1*DD2)
#define B_WK   (B_W + (size_t)2*DD2)
#define B_WV   (B_W + (size_t)3*DD2)
#define B_W1   (B_W + (size_t)4*DD2)
#define B_W2   (B_W + (size_t)5*DD2)
#define B_W2T  (B_W + (size_t)6*DD2)
#define B_W1FH (B_W + (size_t)7*DD2)
#define B_W1FL (B_W + (size_t)8*DD2)
#define B_W2FH (B_W + (size_t)9*DD2)
#define B_W2FL (B_W + (size_t)10*DD2)
#define B_TOTAL (B_W + (size_t)11*DD2)
__device__ __nv_bfloat16 g_bf[B_TOTAL];

// ---------------- PTX helpers ----------------
__device__ __forceinline__ uint32_t smem_u32(const void* p) {
    uint32_t a;
    asm("{ .reg .u64 t; cvta.to.shared.u64 t, %1; cvt.u32.u64 %0, t; }" : "=r"(a) : "l"(p));
    return a;
}
__device__ __forceinline__ void cp16(uint32_t s, const void* g) {
    asm volatile("cp.async.cg.shared.global [%0], [%1], 16;" :: "r"(s), "l"(g) : "memory");
}
__device__ __forceinline__ void cp_commit() {
    asm volatile("cp.async.commit_group;" ::: "memory");
}
__device__ __forceinline__ void ldm4(uint32_t* r, uint32_t a) {
    asm volatile("ldmatrix.sync.aligned.m8n8.x4.shared.b16 {%0,%1,%2,%3}, [%4];"
                 : "=r"(r[0]), "=r"(r[1]), "=r"(r[2]), "=r"(r[3]) : "r"(a));
}
__device__ __forceinline__ void mma16816(float* d, const uint32_t* a, uint32_t b0, uint32_t b1) {
    asm volatile("mma.sync.aligned.m16n8k16.row.col.f32.bf16.bf16.f32 "
        "{%0,%1,%2,%3}, {%4,%5,%6,%7}, {%8,%9}, {%0,%1,%2,%3};"
        : "+f"(d[0]), "+f"(d[1]), "+f"(d[2]), "+f"(d[3])
        : "r"(a[0]), "r"(a[1]), "r"(a[2]), "r"(a[3]), "r"(b0), "r"(b1));
}
__device__ __forceinline__ uint32_t swz(int row, int c) {
    return (uint32_t)(row * 64 + ((c ^ (row & 3)) << 4));
}

// ---------------- plain GEMM: 512 threads, block 256x128, warp 64x32, NS=4 ----------------
__global__ void __launch_bounds__(512, 1) gemm_512(
    const __nv_bfloat16* __restrict__ A, const __nv_bfloat16* __restrict__ B,
    float* __restrict__ C, const float* __restrict__ bias, int Nw, int K)
{
    extern __shared__ __align__(128) char dynsm[];
    constexpr int NS = 4;
    constexpr uint32_t STG = 24576u;     // A 16KB + B 8KB
    const int tid = threadIdx.x;
    const int lane = tid & 31, wid = tid >> 5;
    const int wr = wid >> 2, wc = wid & 3;     // 4x4 warps
    const int m0 = blockIdx.y * 256, n0 = blockIdx.x * 128;
    const uint32_t smA = smem_u32(dynsm);

    // cp.async: A 2 chunks, B 1 chunk per thread
    uint32_t soA[2], soB; size_t goA[2], goB;
#pragma unroll
    for (int i = 0; i < 2; i++) {
        int ch = i * 512 + tid, row = ch >> 2, c = ch & 3;
        soA[i] = swz(row, c);
        goA[i] = (size_t)(m0 + row) * K + c * 8;
    }
    {
        int row = tid >> 2, c = tid & 3;
        soB = swz(row, c);
        goB = (size_t)(n0 + row) * K + c * 8;
    }
    auto issue = [&](int ck) {
        uint32_t sb = smA + (uint32_t)(ck % NS) * STG;
        int k0 = ck << 5;
#pragma unroll
        for (int i = 0; i < 2; i++) cp16(sb + soA[i], A + goA[i] + k0);
        cp16(sb + 16384u + soB, B + goB + k0);
        cp_commit();
    };

    const int laA = lane & 15, lcA = lane >> 4;
    const int laB = (lane & 7) + ((lane >> 4) << 3);
    const int lcB = (lane >> 3) & 1;

    float acc[4][4][4];
#pragma unroll
    for (int mt = 0; mt < 4; mt++)
#pragma unroll
        for (int nt = 0; nt < 4; nt++)
#pragma unroll
            for (int j = 0; j < 4; j++) acc[mt][nt][j] = 0.f;

    const int nk = K >> 5;
#pragma unroll
    for (int p = 0; p < NS - 1; p++) issue(p);

    for (int ck = 0; ck < nk; ck++) {
        if (ck < nk - 2) asm volatile("cp.async.wait_group 2;" ::: "memory");
        else             asm volatile("cp.async.wait_group 0;" ::: "memory");
        __syncthreads();
        if (ck + NS - 1 < nk) issue(ck + NS - 1);   // prefetch early (stage ck-1 safe post-sync)

        uint32_t sb = smA + (uint32_t)(ck % NS) * STG;
#pragma unroll
        for (int ks = 0; ks < 2; ks++) {
            uint32_t af[4][4], bf[2][4];
#pragma unroll
            for (int mt = 0; mt < 4; mt++)
                ldm4(af[mt], sb + swz(wr * 64 + mt * 16 + laA, ks * 2 + lcA));
#pragma unroll
            for (int bt = 0; bt < 2; bt++)
                ldm4(bf[bt], sb + 16384u + swz(wc * 32 + bt * 16 + laB, ks * 2 + lcB));
#pragma unroll
            for (int mt = 0; mt < 4; mt++)
#pragma unroll
                for (int nt = 0; nt < 4; nt++) {
                    const uint32_t* bp = bf[nt >> 1];
                    if (nt & 1) mma16816(acc[mt][nt], af[mt], bp[2], bp[3]);
                    else        mma16816(acc[mt][nt], af[mt], bp[0], bp[1]);
                }
        }
    }

#pragma unroll
    for (int mt = 0; mt < 4; mt++) {
        int r = m0 + wr * 64 + mt * 16 + (lane >> 2);
#pragma unroll
        for (int nt = 0; nt < 4; nt++) {
            int col = n0 + wc * 32 + nt * 8 + (lane & 3) * 2;
            float bx = 0.f, by = 0.f;
            if (bias) { bx = bias[col]; by = bias[col + 1]; }
            *(float2*)(C + (size_t)r * Nw + col) =
                make_float2(acc[mt][nt][0] + bx, acc[mt][nt][1] + by);
            *(float2*)(C + (size_t)(r + 8) * Nw + col) =
                make_float2(acc[mt][nt][2] + bx, acc[mt][nt][3] + by);
        }
    }
}

// ---------------- fused split GEMM: C = AhBh^T + AhBl^T + AlBh^T (+bias) ----------------
// Block 128x128, BK=32, NS=3, 8 warps, warp tile 32x64.
__global__ void __launch_bounds__(256) gemm_split(
    const __nv_bfloat16* __restrict__ A, const __nv_bfloat16* __restrict__ Alo,
    const __nv_bfloat16* __restrict__ B, const __nv_bfloat16* __restrict__ Blo,
    float* __restrict__ C, const float* __restrict__ bias, int Nw, int K)
{
    extern __shared__ __align__(128) char dynsm[];
    constexpr int NS = 3;
    constexpr uint32_t STG = 32768u;
    const int tid = threadIdx.x;
    const int lane = tid & 31, wid = tid >> 5;
    const int wr = wid >> 1, wc = wid & 1;
    const int m0 = blockIdx.y * 128, n0 = blockIdx.x * 128;
    const uint32_t smA = smem_u32(dynsm);

    uint32_t so[2]; size_t goA[2], goB[2];
#pragma unroll
    for (int i = 0; i < 2; i++) {
        int ch = tid * 2 + i, row = ch >> 2, c = ch & 3;
        so[i] = swz(row, c);
        goA[i] = (size_t)(m0 + row) * K + c * 8;
        goB[i] = (size_t)(n0 + row) * K + c * 8;
    }
    auto issue = [&](int ck) {
        uint32_t sb = smA + (uint32_t)(ck % NS) * STG;
        int k0 = ck << 5;
#pragma unroll
        for (int i = 0; i < 2; i++) cp16(sb + so[i], A + goA[i] + k0);
#pragma unroll
        for (int i = 0; i < 2; i++) cp16(sb + 8192u + so[i], B + goB[i] + k0);
#pragma unroll
        for (int i = 0; i < 2; i++) cp16(sb + 16384u + so[i], Alo + goA[i] + k0);
#pragma unroll
        for (int i = 0; i < 2; i++) cp16(sb + 24576u + so[i], Blo + goB[i] + k0);
        cp_commit();
    };

    const int laA = lane & 15, lcA = lane >> 4;
    const int laB = (lane & 7) + ((lane >> 4) << 3);
    const int lcB = (lane >> 3) & 1;

    float acc[2][8][4];
#pragma unroll
    for (int mt = 0; mt < 2; mt++)
#pragma unroll
        for (int nt = 0; nt < 8; nt++)
#pragma unroll
            for (int j = 0; j < 4; j++) acc[mt][nt][j] = 0.f;

    const int nk = K >> 5;
#pragma unroll
    for (int p = 0; p < NS - 1; p++) issue(p);

    for (int ck = 0; ck < nk; ck++) {
        if (ck < nk - 1) asm volatile("cp.async.wait_group 1;" ::: "memory");
        else             asm volatile("cp.async.wait_group 0;" ::: "memory");
        __syncthreads();
        if (ck + NS - 1 < nk) issue(ck + NS - 1);

        uint32_t sb = smA + (uint32_t)(ck % NS) * STG;
#pragma unroll
        for (int ks = 0; ks < 2; ks++) {
            uint32_t af[2][4], bf[4][4];
#pragma unroll
            for (int mt = 0; mt < 2; mt++)
                ldm4(af[mt], sb + swz(wr * 32 + mt * 16 + laA, ks * 2 + lcA));
#pragma unroll
            for (int bt = 0; bt < 4; bt++)
                ldm4(bf[bt], sb + 8192u + swz(wc * 64 + bt * 16 + laB, ks * 2 + lcB));
#pragma unroll
            for (int mt = 0; mt < 2; mt++)
#pragma unroll
                for (int nt = 0; nt < 8; nt++) {
                    const uint32_t* bp = bf[nt >> 1];
                    if (nt & 1) mma16816(acc[mt][nt], af[mt], bp[2], bp[3]);
                    else        mma16816(acc[mt][nt], af[mt], bp[0], bp[1]);
                }
            uint32_t afl[2][4], bfl[4][4];
#pragma unroll
            for (int mt = 0; mt < 2; mt++)
                ldm4(afl[mt], sb + 16384u + swz(wr * 32 + mt * 16 + laA, ks * 2 + lcA));
#pragma unroll
            for (int bt = 0; bt < 4; bt++)
                ldm4(bfl[bt], sb + 24576u + swz(wc * 64 + bt * 16 + laB, ks * 2 + lcB));
#pragma unroll
            for (int mt = 0; mt < 2; mt++)
#pragma unroll
                for (int nt = 0; nt < 8; nt++) {
                    const uint32_t* bp = bfl[nt >> 1];
                    if (nt & 1) mma16816(acc[mt][nt], af[mt], bp[2], bp[3]);
                    else        mma16816(acc[mt][nt], af[mt], bp[0], bp[1]);
                }
#pragma unroll
            for (int mt = 0; mt < 2; mt++)
#pragma unroll
                for (int nt = 0; nt < 8; nt++) {
                    const uint32_t* bp = bf[nt >> 1];
                    if (nt & 1) mma16816(acc[mt][nt], afl[mt], bp[2], bp[3]);
                    else        mma16816(acc[mt][nt], afl[mt], bp[0], bp[1]);
                }
        }
    }

#pragma unroll
    for (int mt = 0; mt < 2; mt++) {
        int r = m0 + wr * 32 + mt * 16 + (lane >> 2);
#pragma unroll
        for (int nt = 0; nt < 8; nt++) {
            int col = n0 + wc * 64 + nt * 8 + (lane & 3) * 2;
            float bx = 0.f, by = 0.f;
            if (bias) { bx = bias[col]; by = bias[col + 1]; }
            *(float2*)(C + (size_t)r * Nw + col) =
                make_float2(acc[mt][nt][0] + bx, acc[mt][nt][1] + by);
            *(float2*)(C + (size_t)(r + 8) * Nw + col) =
                make_float2(acc[mt][nt][2] + bx, acc[mt][nt][3] + by);
        }
    }
}

// ---------------- conversions ----------------
__global__ void __launch_bounds__(256) cvt_k(const float4* __restrict__ in,
                                             __nv_bfloat162* __restrict__ out)
{
    size_t i = (size_t)blockIdx.x * 256 + threadIdx.x;
    float4 v = in[i];
    out[2*i]   = __floats2bfloat162_rn(v.x, v.y);
    out[2*i+1] = __floats2bfloat162_rn(v.z, v.w);
}
__global__ void __launch_bounds__(256) cvt_split_k(const float4* __restrict__ in,
                                                   __nv_bfloat162* __restrict__ oh,
                                                   __nv_bfloat162* __restrict__ ol)
{
    size_t i = (size_t)blockIdx.x * 256 + threadIdx.x;
    float4 v = in[i];
    float f[4] = { v.x, v.y, v.z, v.w };
    __nv_bfloat16 h[4], l[4];
#pragma unroll
    for (int j = 0; j < 4; j++) {
        h[j] = __float2bfloat16(f[j]);
        l[j] = __float2bfloat16(f[j] - __bfloat162float(h[j]));
    }
    oh[2*i]   = __nv_bfloat162(h[0], h[1]);
    oh[2*i+1] = __nv_bfloat162(h[2], h[3]);
    ol[2*i]   = __nv_bfloat162(l[0], l[1]);
    ol[2*i+1] = __nv_bfloat162(l[2], l[3]);
}
__global__ void __launch_bounds__(256) cvtT_k(const float* __restrict__ in,
                                              __nv_bfloat16* __restrict__ out, int R, int Cc)
{
    __shared__ float tile[32][33];
    int cb = blockIdx.x * 32, rb = blockIdx.y * 32;
    int tx = threadIdx.x & 31, ty = threadIdx.x >> 5;
#pragma unroll
    for (int i = 0; i < 32; i += 8)
        tile[ty + i][tx] = in[(size_t)(rb + ty + i) * Cc + cb + tx];
    __syncthreads();
#pragma unroll
    for (int i = 0; i < 32; i += 8)
        out[(size_t)(cb + ty + i) * R + rb + tx] = __float2bfloat16(tile[tx][ty + i]);
}

// ---------------- fused row-l2norm ----------------
__global__ void __launch_bounds__(256) rownorm_split_k(const float* __restrict__ X,
                                                       __nv_bfloat16* __restrict__ oh,
                                                       __nv_bfloat16* __restrict__ ol)
{
    __shared__ float red[256];
    int r = blockIdx.x, t = threadIdx.x;
    float ss = 0.f;
    for (int c = t; c < DD; c += 256) { float v = X[(size_t)r * DD + c]; ss += v * v; }
    red[t] = ss; __syncthreads();
    for (int s = 128; s > 0; s >>= 1) { if (t < s) red[t] += red[t + s]; __syncthreads(); }
    float sc = 1.0f / fmaxf(sqrtf(red[0]), 1e-12f);
    for (int c = t; c < DD; c += 256) {
        float v = X[(size_t)r * DD + c] * sc;
        __nv_bfloat16 h = __float2bfloat16(v);
        oh[(size_t)r * DD + c] = h;
        ol[(size_t)r * DD + c] = __float2bfloat16(v - __bfloat162float(h));
    }
}
__global__ void __launch_bounds__(256) rownorm_bf_k(float* __restrict__ X,
                                                    __nv_bfloat16* __restrict__ ob)
{
    __shared__ float red[256];
    int r = blockIdx.x, t = threadIdx.x;
    float ss = 0.f;
    for (int c = t; c < DD; c += 256) { float v = X[(size_t)r * DD + c]; ss += v * v; }
    red[t] = ss; __syncthreads();
    for (int s = 128; s > 0; s >>= 1) { if (t < s) red[t] += red[t + s]; __syncthreads(); }
    float sc = 1.0f / fmaxf(sqrtf(red[0]), 1e-12f);
    for (int c = t; c < DD; c += 256) {
        float v = X[(size_t)r * DD + c] * sc;
        X[(size_t)r * DD + c] = v;
        ob[(size_t)r * DD + c] = __float2bfloat16(v);
    }
}

// ---------------- fused elementwise ----------------
__global__ void __launch_bounds__(256) silu_bf_k(const float4* __restrict__ h,
                                                 float4* __restrict__ a,
                                                 __nv_bfloat162* __restrict__ ab)
{
    size_t i = (size_t)blockIdx.x * 256 + threadIdx.x;
    float4 x = h[i], o;
    o.x = x.x / (1.0f + expf(-x.x)); o.y = x.y / (1.0f + expf(-x.y));
    o.z = x.z / (1.0f + expf(-x.z)); o.w = x.w / (1.0f + expf(-x.w));
    a[i] = o;
    ab[2*i]   = __floats2bfloat162_rn(o.x, o.y);
    ab[2*i+1] = __floats2bfloat162_rn(o.z, o.w);
}
__global__ void __launch_bounds__(256) silu_split_k(const float4* __restrict__ h,
                                                    __nv_bfloat162* __restrict__ oh,
                                                    __nv_bfloat162* __restrict__ ol)
{
    size_t i = (size_t)blockIdx.x * 256 + threadIdx.x;
    float4 x = h[i];
    float f[4] = { x.x / (1.0f + expf(-x.x)), x.y / (1.0f + expf(-x.y)),
                   x.z / (1.0f + expf(-x.z)), x.w / (1.0f + expf(-x.w)) };
    __nv_bfloat16 hh[4], ll[4];
#pragma unroll
    for (int j = 0; j < 4; j++) {
        hh[j] = __float2bfloat16(f[j]);
        ll[j] = __float2bfloat16(f[j] - __bfloat162float(hh[j]));
    }
    oh[2*i]   = __nv_bfloat162(hh[0], hh[1]);
    oh[2*i+1] = __nv_bfloat162(hh[2], hh[3]);
    ol[2*i]   = __nv_bfloat162(ll[0], ll[1]);
    ol[2*i+1] = __nv_bfloat162(ll[2], ll[3]);
}
__global__ void __launch_bounds__(256) make_dy_bf_k(const float4* __restrict__ v,
                                                    float4* __restrict__ y,
                                                    __nv_bfloat162* __restrict__ ob)
{
    size_t i = (size_t)blockIdx.x * 256 + threadIdx.x;
    const float sc = 2.0f / (float)SD;
    float4 yy = y[i], vv = v[i], o;
    o.x = (yy.x - vv.x) * sc; o.y = (yy.y - vv.y) * sc;
    o.z = (yy.z - vv.z) * sc; o.w = (yy.w - vv.w) * sc;
    y[i] = o;
    ob[2*i]   = __floats2bfloat162_rn(o.x, o.y);
    ob[2*i+1] = __floats2bfloat162_rn(o.z, o.w);
}
__global__ void __launch_bounds__(256) make_dh_k(const float4* __restrict__ h,
                                                 float4* __restrict__ dh)
{
    size_t i = (size_t)blockIdx.x * 256 + threadIdx.x;
    float4 x = h[i], d = dh[i];
    float f[4] = { x.x, x.y, x.z, x.w };
    float g[4] = { d.x, d.y, d.z, d.w };
#pragma unroll
    for (int j = 0; j < 4; j++) {
        float sg = 1.0f / (1.0f + expf(-f[j]));
        g[j] *= sg * (1.0f + f[j] * (1.0f - sg));
    }
    dh[i] = make_float4(g[0], g[1], g[2], g[3]);
}
__global__ void __launch_bounds__(256) colsum_k(const float* __restrict__ M, float* __restrict__ out)
{
    int c = blockIdx.x * 256 + threadIdx.x;
    float s0 = 0.f, s1 = 0.f, s2 = 0.f, s3 = 0.f;
    for (int r = 0; r < SS; r += 4) {
        s0 += M[(size_t)(r+0)*DD + c]; s1 += M[(size_t)(r+1)*DD + c];
        s2 += M[(size_t)(r+2)*DD + c]; s3 += M[(size_t)(r+3)*DD + c];
    }
    out[c] = (s0 + s1) + (s2 + s3);
}
__global__ void __launch_bounds__(256) alpha_partial_k(const float* __restrict__ x,
                                                       const float* __restrict__ aw,
                                                       float* __restrict__ part)
{
    __shared__ float red[256];
    int b = blockIdx.x, t = threadIdx.x;
    size_t base = (size_t)b * 8192;
    float s = 0.f;
    for (int i = t; i < 8192; i += 256) s += x[base + i] * aw[i & (DD - 1)];
    red[t] = s; __syncthreads();
    for (int k = 128; k > 0; k >>= 1) { if (t < k) red[t] += red[t + k]; __syncthreads(); }
    if (t == 0) part[b] = red[0];
}
__global__ void __launch_bounds__(256) alpha_final_k(const float* __restrict__ ab,
                                                     const float* __restrict__ part,
                                                     float* __restrict__ alpha)
{
    __shared__ float red[256];
    int t = threadIdx.x;
    float s = 0.f;
    for (int i = t; i < 2048; i += 256) s += part[i];
    red[t] = s; __syncthreads();
    for (int k = 128; k > 0; k >>= 1) { if (t < k) red[t] += red[t + k]; __syncthreads(); }
    if (t == 0) alpha[0] = 1.0f / (1.0f + expf(-(red[0] / (float)SS + ab[0])));
}
__global__ void __launch_bounds__(256) fastw_split_k(const float4* __restrict__ W,
                                                     const float4* __restrict__ Gm,
                                                     float4* __restrict__ Wf,
                                                     __nv_bfloat162* __restrict__ oh,
                                                     __nv_bfloat162* __restrict__ ol,
                                                     const float* __restrict__ alpha)
{
    size_t i = (size_t)blockIdx.x * 256 + threadIdx.x;
    float am1 = 1.0f - alpha[0];
    float4 w = W[i], g = Gm[i], o;
    o.x = am1 * w.x - INNER_LR * g.x; o.y = am1 * w.y - INNER_LR * g.y;
    o.z = am1 * w.z - INNER_LR * g.z; o.w = am1 * w.w - INNER_LR * g.w;
    Wf[i] = o;
    float f[4] = { o.x, o.y, o.z, o.w };
    __nv_bfloat16 hh[4], ll[4];
#pragma unroll
    for (int j = 0; j < 4; j++) {
        hh[j] = __float2bfloat16(f[j]);
        ll[j] = __float2bfloat16(f[j] - __bfloat162float(hh[j]));
    }
    oh[2*i]   = __nv_bfloat162(hh[0], hh[1]);
    oh[2*i+1] = __nv_bfloat162(hh[2], hh[3]);
    ol[2*i]   = __nv_bfloat162(ll[0], ll[1]);
    ol[2*i+1] = __nv_bfloat162(ll[2], ll[3]);
}
__global__ void __launch_bounds__(256) fastb_k(
    const float* __restrict__ b1, const float* __restrict__ gb1, float* __restrict__ b1f,
    const float* __restrict__ b2, const float* __restrict__ gb2, float* __restrict__ b2f,
    const float* __restrict__ alpha)
{
    int i = blockIdx.x * 256 + threadIdx.x;
    float am1 = 1.0f - alpha[0];
    b1f[i] = am1 * b1[i] - INNER_LR * gb1[i];
    b2f[i] = am1 * b2[i] - INNER_LR * gb2[i];
}

// ---------------- launch ----------------
extern "C" void kernel_launch(void* const* d_in, const int* in_sizes, int n_in,
                              void* d_out, int out_size)
{
    const float* x   = (const float*)d_in[0];
    const float* W_Q = (const float*)d_in[1];
    const float* W_K = (const float*)d_in[2];
    const float* W_V = (const float*)d_in[3];
    const float* aw  = (const float*)d_in[4];
    const float* ab  = (const float*)d_in[5];
    const float* W1  = (const float*)d_in[6];
    const float* b1  = (const float*)d_in[7];
    const float* W2  = (const float*)d_in[8];
    const float* b2  = (const float*)d_in[9];
    float* out = (float*)d_out;

    float* F; __nv_bfloat16* Bp;
    cudaGetSymbolAddress((void**)&F, g_f32);
    cudaGetSymbolAddress((void**)&Bp, g_bf);

    const int SMB = 4 * 24576;   // gemm_512: NS=4, 96KB
    const int SMS = 3 * 32768;   // gemm_split: NS=3, 96KB
    cudaFuncSetAttribute((const void*)gemm_512, cudaFuncAttributeMaxDynamicSharedMemorySize, SMB);
    cudaFuncSetAttribute((const void*)gemm_split, cudaFuncAttributeMaxDynamicSharedMemorySize, SMS);

    dim3 blk(256), blk5(512);
    dim3 gSDb(DD / 128, SS / 256);   // gemm_512: [S,D] outputs
    dim3 gDDb(DD / 128, DD / 256);   // gemm_512: [D,D] outputs
    dim3 gSDs(DD / 128, SS / 128);   // split
    int ew4 = SD / 1024, ewW4 = DD2 / 1024;
    dim3 tSD(DD / 32, SS / 32), tDD(DD / 32, DD / 32);

    // input conversions
    cvt_split_k<<<ew4, blk>>>((const float4*)x, (__nv_bfloat162*)(Bp+B_XH), (__nv_bfloat162*)(Bp+B_XL));
    cvt_split_k<<<ewW4, blk>>>((const float4*)W_Q, (__nv_bfloat162*)(Bp+B_WQH), (__nv_bfloat162*)(Bp+B_WQL));
    cvt_k<<<ewW4, blk>>>((const float4*)W_K, (__nv_bfloat162*)(Bp+B_WK));
    cvt_k<<<ewW4, blk>>>((const float4*)W_V, (__nv_bfloat162*)(Bp+B_WV));
    cvt_k<<<ewW4, blk>>>((const float4*)W1, (__nv_bfloat162*)(Bp+B_W1));
    cvt_k<<<ewW4, blk>>>((const float4*)W2, (__nv_bfloat162*)(Bp+B_W2));
    cvtT_k<<<tDD, blk>>>(W2, Bp + B_W2T, DD, DD);

    // alpha (exact fp32)
    alpha_partial_k<<<2048, blk>>>(x, aw, F + F_PART);
    alpha_final_k<<<1, blk>>>(ab, F + F_PART, F + F_ALPHA);

    // q (split), k, v
    gemm_split<<<gSDs, blk, SMS>>>(Bp+B_XH, Bp+B_XL, Bp+B_WQH, Bp+B_WQL, F+F_Q, nullptr, DD, DD);
    gemm_512<<<gSDb, blk5, SMB>>>(Bp+B_XH, Bp+B_WK, F+F_K, nullptr, DD, DD);
    gemm_512<<<gSDb, blk5, SMB>>>(Bp+B_XH, Bp+B_WV, F+F_V, nullptr, DD, DD);
    rownorm_split_k<<<SS, blk>>>(F + F_Q, Bp + B_QH, Bp + B_QL);
    rownorm_bf_k<<<SS, blk>>>(F + F_K, Bp + B_K);
    cvtT_k<<<tSD, blk>>>(F + F_K, Bp + B_KT, SS, DD);

    // forward MLP on k
    gemm_512<<<gSDb, blk5, SMB>>>(Bp+B_K, Bp+B_W1, F+F_H, b1, DD, DD);
    silu_bf_k<<<ew4, blk>>>((const float4*)(F+F_H), (float4*)(F+F_A), (__nv_bfloat162*)(Bp+B_A));
    cvtT_k<<<tSD, blk>>>(F + F_A, Bp + B_AT, SS, DD);
    gemm_512<<<gSDb, blk5, SMB>>>(Bp+B_A, Bp+B_W2, F+F_DY, b2, DD, DD);
    make_dy_bf_k<<<ew4, blk>>>((const float4*)(F+F_V), (float4*)(F+F_DY), (__nv_bfloat162*)(Bp+B_DY));
    cvtT_k<<<tSD, blk>>>(F + F_DY, Bp + B_DYT, SS, DD);

    // gW2 = dy^T @ a ; gb2
    gemm_512<<<gDDb, blk5, SMB>>>(Bp+B_DYT, Bp+B_AT, F+F_GW2, nullptr, DD, SS);
    colsum_k<<<DD / 256, blk>>>(F + F_DY, F + F_GB2);

    // dh = (dy @ W2) * dsilu(h) ; gW1 = dh^T @ k ; gb1
    gemm_512<<<gSDb, blk5, SMB>>>(Bp+B_DY, Bp+B_W2T, F+F_DH, nullptr, DD, DD);
    make_dh_k<<<ew4, blk>>>((const float4*)(F+F_H), (float4*)(F+F_DH));
    cvtT_k<<<tSD, blk>>>(F + F_DH, Bp + B_DHT, SS, DD);
    gemm_512<<<gDDb, blk5, SMB>>>(Bp+B_DHT, Bp+B_KT, F+F_GW1, nullptr, DD, SS);
    colsum_k<<<DD / 256, blk>>>(F + F_DH, F + F_GB1);

    // fast weights (+ fused split conversion)
    fastw_split_k<<<ewW4, blk>>>((const float4*)W1, (const float4*)(F+F_GW1), (float4*)(F+F_W1F),
                                 (__nv_bfloat162*)(Bp+B_W1FH), (__nv_bfloat162*)(Bp+B_W1FL), F+F_ALPHA);
    fastw_split_k<<<ewW4, blk>>>((const float4*)W2, (const float4*)(F+F_GW2), (float4*)(F+F_W2F),
                                 (__nv_bfloat162*)(Bp+B_W2FH), (__nv_bfloat162*)(Bp+B_W2FL), F+F_ALPHA);
    fastb_k<<<DD / 256, blk>>>(b1, F+F_GB1, F+F_B1F, b2, F+F_GB2, F+F_B2F, F+F_ALPHA);

    // retrieve (split precision)
    gemm_split<<<gSDs, blk, SMS>>>(Bp+B_QH, Bp+B_QL, Bp+B_W1FH, Bp+B_W1FL, F+F_H, F+F_B1F, DD, DD);
    silu_split_k<<<ew4, blk>>>((const float4*)(F+F_H), (__nv_bfloat162*)(Bp+B_ARH), (__nv_bfloat162*)(Bp+B_ARL));
    gemm_split<<<gSDs, blk, SMS>>>(Bp+B_ARH, Bp+B_ARL, Bp+B_W2FH, Bp+B_W2FL, out, F+F_B2F, DD, DD);
}

// round 16
// speedup vs baseline: 1.1818x; 1.1818x over previous
#include <cuda_runtime.h>
#include <cuda_bf16.h>
#include <math.h>
#include <stdint.h>

#define DD 2048
#define SS 8192
#define SD (SS*DD)
#define DD2 (DD*DD)
#define INNER_LR 0.01f

// ---------------- scratch arenas ----------------
#define F_Q   ((size_t)0*SD)
#define F_K   ((size_t)1*SD)
#define F_V   ((size_t)2*SD)
#define F_H   ((size_t)3*SD)
#define F_A   ((size_t)4*SD)
#define F_DY  ((size_t)5*SD)
#define F_DH  ((size_t)6*SD)
#define F_GW1 ((size_t)7*SD)
#define F_GW2 (F_GW1 + DD2)
#define F_W1F (F_GW2 + DD2)
#define F_W2F (F_W1F + DD2)
#define F_B1F (F_W2F + DD2)
#define F_B2F (F_B1F + DD)
#define F_GB1 (F_B2F + DD)
#define F_GB2 (F_GB1 + DD)
#define F_PART (F_GB2 + DD)
#define F_ALPHA (F_PART + 2048)
#define F_TOTAL (F_ALPHA + 64)
__device__ float g_f32[F_TOTAL];

#define B_XH   ((size_t)0*SD)
#define B_XL   ((size_t)1*SD)
#define B_QH   ((size_t)2*SD)
#define B_QL   ((size_t)3*SD)
#define B_K    ((size_t)4*SD)
#define B_KT   ((size_t)5*SD)
#define B_A    ((size_t)6*SD)
#define B_AT   ((size_t)7*SD)
#define B_DY   ((size_t)8*SD)
#define B_DYT  ((size_t)9*SD)
#define B_DHT  ((size_t)10*SD)
#define B_ARH  ((size_t)11*SD)
#define B_ARL  ((size_t)12*SD)
#define B_W    ((size_t)13*SD)
#define B_WQH  (B_W + (size_t)0*DD2)
#define B_WQL  (B_W + (size_t)1*DD2)
#define B_WK   (B_W + (size_t)2*DD2)
#define B_WV   (B_W + (size_t)3*DD2)
#define B_W1   (B_W + (size_t)4*DD2)
#define B_W2   (B_W + (size_t)5*DD2)
#define B_W2T  (B_W + (size_t)6*DD2)
#define B_W1FH (B_W + (size_t)7*DD2)
#define B_W1FL (B_W + (size_t)8*DD2)
#define B_W2FH (B_W + (size_t)9*DD2)
#define B_W2FL (B_W + (size_t)10*DD2)
#define B_TOTAL (B_W + (size_t)11*DD2)
__device__ __nv_bfloat16 g_bf[B_TOTAL];

// ---------------- PTX helpers ----------------
__device__ __forceinline__ uint32_t smem_u32(const void* p) {
    uint32_t a;
    asm("{ .reg .u64 t; cvta.to.shared.u64 t, %1; cvt.u32.u64 %0, t; }" : "=r"(a) : "l"(p));
    return a;
}
__device__ __forceinline__ void cp16(uint32_t s, const void* g) {
    asm volatile("cp.async.cg.shared.global [%0], [%1], 16;" :: "r"(s), "l"(g) : "memory");
}
__device__ __forceinline__ void cp_commit() {
    asm volatile("cp.async.commit_group;" ::: "memory");
}
__device__ __forceinline__ void ldm4(uint32_t* r, uint32_t a) {
    asm volatile("ldmatrix.sync.aligned.m8n8.x4.shared.b16 {%0,%1,%2,%3}, [%4];"
                 : "=r"(r[0]), "=r"(r[1]), "=r"(r[2]), "=r"(r[3]) : "r"(a));
}
__device__ __forceinline__ void mma16816(float* d, const uint32_t* a, uint32_t b0, uint32_t b1) {
    asm volatile("mma.sync.aligned.m16n8k16.row.col.f32.bf16.bf16.f32 "
        "{%0,%1,%2,%3}, {%4,%5,%6,%7}, {%8,%9}, {%0,%1,%2,%3};"
        : "+f"(d[0]), "+f"(d[1]), "+f"(d[2]), "+f"(d[3])
        : "r"(a[0]), "r"(a[1]), "r"(a[2]), "r"(a[3]), "r"(b0), "r"(b1));
}
// 64B-row swizzle (BK=32 tiles, gemm_split)
__device__ __forceinline__ uint32_t swz(int row, int c) {
    return (uint32_t)(row * 64 + ((c ^ (row & 3)) << 4));
}
// 128B-row swizzle (BK=64 tiles, gemm_big)
__device__ __forceinline__ uint32_t swz8(int row, int c) {
    return (uint32_t)(row * 128 + ((c ^ (row & 7)) << 4));
}

// ---------------- plain GEMM: block 256x128, 8 warps, warp 64x64, BK=64, NS=3 ----------------
__global__ void __launch_bounds__(256) gemm_big(
    const __nv_bfloat16* __restrict__ A, const __nv_bfloat16* __restrict__ B,
    float* __restrict__ C, const float* __restrict__ bias, int Nw, int K)
{
    extern __shared__ __align__(128) char dynsm[];
    constexpr int NS = 3;
    constexpr uint32_t STG = 49152u;     // A 32KB + B 16KB per stage
    const int tid = threadIdx.x;
    const int lane = tid & 31, wid = tid >> 5;
    const int wr = wid >> 1, wc = wid & 1;       // 4x2 warps, warp tile 64x64
    const int m0 = blockIdx.y * 256, n0 = blockIdx.x * 128;
    const uint32_t smA = smem_u32(dynsm);

    // cp.async: base offsets; chunk i covers rows i*32 + (tid>>3), col chunk tid&7
    const int r0 = tid >> 3, c0 = tid & 7;
    const uint32_t soA = swz8(r0, c0);
    const size_t goA = (size_t)(m0 + r0) * K + c0 * 8;
    const size_t goB = (size_t)(n0 + r0) * K + c0 * 8;
    const size_t rowstep = (size_t)32 * K;

    auto issue = [&](int ck) {
        uint32_t sb = smA + (uint32_t)(ck % NS) * STG;
        int k0 = ck << 6;
#pragma unroll
        for (int i = 0; i < 8; i++)
            cp16(sb + soA + (uint32_t)i * 4096u, A + goA + (size_t)i * rowstep + k0);
#pragma unroll
        for (int i = 0; i < 4; i++)
            cp16(sb + 32768u + soA + (uint32_t)i * 4096u, B + goB + (size_t)i * rowstep + k0);
        cp_commit();
    };

    const int laA = lane & 15, lcA = lane >> 4;
    const int laB = (lane & 7) + ((lane >> 4) << 3);
    const int lcB = (lane >> 3) & 1;

    float acc[4][8][4];
#pragma unroll
    for (int mt = 0; mt < 4; mt++)
#pragma unroll
        for (int nt = 0; nt < 8; nt++)
#pragma unroll
            for (int j = 0; j < 4; j++) acc[mt][nt][j] = 0.f;

    const int nk = K >> 6;
    issue(0); issue(1);

    for (int ck = 0; ck < nk; ck++) {
        if (ck < nk - 1) asm volatile("cp.async.wait_group 1;" ::: "memory");
        else             asm volatile("cp.async.wait_group 0;" ::: "memory");
        __syncthreads();

        uint32_t sb = smA + (uint32_t)(ck % NS) * STG;
#pragma unroll
        for (int ks = 0; ks < 4; ks++) {
            uint32_t af[4][4], bf[4][4];
#pragma unroll
            for (int mt = 0; mt < 4; mt++)
                ldm4(af[mt], sb + swz8(wr * 64 + mt * 16 + laA, ks * 2 + lcA));
#pragma unroll
            for (int bt = 0; bt < 4; bt++)
                ldm4(bf[bt], sb + 32768u + swz8(wc * 64 + bt * 16 + laB, ks * 2 + lcB));
#pragma unroll
            for (int mt = 0; mt < 4; mt++)
#pragma unroll
                for (int nt = 0; nt < 8; nt++) {
                    const uint32_t* bp = bf[nt >> 1];
                    if (nt & 1) mma16816(acc[mt][nt], af[mt], bp[2], bp[3]);
                    else        mma16816(acc[mt][nt], af[mt], bp[0], bp[1]);
                }
        }
        if (ck + NS - 1 < nk) issue(ck + NS - 1);
    }

#pragma unroll
    for (int mt = 0; mt < 4; mt++) {
        int r = m0 + wr * 64 + mt * 16 + (lane >> 2);
#pragma unroll
        for (int nt = 0; nt < 8; nt++) {
            int col = n0 + wc * 64 + nt * 8 + (lane & 3) * 2;
            float bx = 0.f, by = 0.f;
            if (bias) { bx = bias[col]; by = bias[col + 1]; }
            *(float2*)(C + (size_t)r * Nw + col) =
                make_float2(acc[mt][nt][0] + bx, acc[mt][nt][1] + by);
            *(float2*)(C + (size_t)(r + 8) * Nw + col) =
                make_float2(acc[mt][nt][2] + bx, acc[mt][nt][3] + by);
        }
    }
}

// ---------------- fused split GEMM: C = AhBh^T + AhBl^T + AlBh^T (+bias) ----------------
// Block 128x128, BK=32, NS=3, 8 warps, warp tile 32x64.  (R14-proven)
__global__ void __launch_bounds__(256) gemm_split(
    const __nv_bfloat16* __restrict__ A, const __nv_bfloat16* __restrict__ Alo,
    const __nv_bfloat16* __restrict__ B, const __nv_bfloat16* __restrict__ Blo,
    float* __restrict__ C, const float* __restrict__ bias, int Nw, int K)
{
    extern __shared__ __align__(128) char dynsm[];
    constexpr int NS = 3;
    constexpr uint32_t STG = 32768u;
    const int tid = threadIdx.x;
    const int lane = tid & 31, wid = tid >> 5;
    const int wr = wid >> 1, wc = wid & 1;
    const int m0 = blockIdx.y * 128, n0 = blockIdx.x * 128;
    const uint32_t smA = smem_u32(dynsm);

    uint32_t so[2]; size_t goA[2], goB[2];
#pragma unroll
    for (int i = 0; i < 2; i++) {
        int ch = tid * 2 + i, row = ch >> 2, c = ch & 3;
        so[i] = swz(row, c);
        goA[i] = (size_t)(m0 + row) * K + c * 8;
        goB[i] = (size_t)(n0 + row) * K + c * 8;
    }
    auto issue = [&](int ck) {
        uint32_t sb = smA + (uint32_t)(ck % NS) * STG;
        int k0 = ck << 5;
#pragma unroll
        for (int i = 0; i < 2; i++) cp16(sb + so[i], A + goA[i] + k0);
#pragma unroll
        for (int i = 0; i < 2; i++) cp16(sb + 8192u + so[i], B + goB[i] + k0);
#pragma unroll
        for (int i = 0; i < 2; i++) cp16(sb + 16384u + so[i], Alo + goA[i] + k0);
#pragma unroll
        for (int i = 0; i < 2; i++) cp16(sb + 24576u + so[i], Blo + goB[i] + k0);
        cp_commit();
    };

    const int laA = lane & 15, lcA = lane >> 4;
    const int laB = (lane & 7) + ((lane >> 4) << 3);
    const int lcB = (lane >> 3) & 1;

    float acc[2][8][4];
#pragma unroll
    for (int mt = 0; mt < 2; mt++)
#pragma unroll
        for (int nt = 0; nt < 8; nt++)
#pragma unroll
            for (int j = 0; j < 4; j++) acc[mt][nt][j] = 0.f;

    const int nk = K >> 5;
    issue(0); issue(1);

    for (int ck = 0; ck < nk; ck++) {
        if (ck < nk - 1) asm volatile("cp.async.wait_group 1;" ::: "memory");
        else             asm volatile("cp.async.wait_group 0;" ::: "memory");
        __syncthreads();

        uint32_t sb = smA + (uint32_t)(ck % NS) * STG;
#pragma unroll
        for (int ks = 0; ks < 2; ks++) {
            uint32_t af[2][4], bf[4][4];
#pragma unroll
            for (int mt = 0; mt < 2; mt++)
                ldm4(af[mt], sb + swz(wr * 32 + mt * 16 + laA, ks * 2 + lcA));
#pragma unroll
            for (int bt = 0; bt < 4; bt++)
                ldm4(bf[bt], sb + 8192u + swz(wc * 64 + bt * 16 + laB, ks * 2 + lcB));
#pragma unroll
            for (int mt = 0; mt < 2; mt++)
#pragma unroll
                for (int nt = 0; nt < 8; nt++) {
                    const uint32_t* bp = bf[nt >> 1];
                    if (nt & 1) mma16816(acc[mt][nt], af[mt], bp[2], bp[3]);
                    else        mma16816(acc[mt][nt], af[mt], bp[0], bp[1]);
                }
            uint32_t afl[2][4], bfl[4][4];
#pragma unroll
            for (int mt = 0; mt < 2; mt++)
                ldm4(afl[mt], sb + 16384u + swz(wr * 32 + mt * 16 + laA, ks * 2 + lcA));
#pragma unroll
            for (int bt = 0; bt < 4; bt++)
                ldm4(bfl[bt], sb + 24576u + swz(wc * 64 + bt * 16 + laB, ks * 2 + lcB));
#pragma unroll
            for (int mt = 0; mt < 2; mt++)
#pragma unroll
                for (int nt = 0; nt < 8; nt++) {
                    const uint32_t* bp = bfl[nt >> 1];
                    if (nt & 1) mma16816(acc[mt][nt], af[mt], bp[2], bp[3]);
                    else        mma16816(acc[mt][nt], af[mt], bp[0], bp[1]);
                }
#pragma unroll
            for (int mt = 0; mt < 2; mt++)
#pragma unroll
                for (int nt = 0; nt < 8; nt++) {
                    const uint32_t* bp = bf[nt >> 1];
                    if (nt & 1) mma16816(acc[mt][nt], afl[mt], bp[2], bp[3]);
                    else        mma16816(acc[mt][nt], afl[mt], bp[0], bp[1]);
                }
        }
        if (ck + NS - 1 < nk) issue(ck + NS - 1);
    }

#pragma unroll
    for (int mt = 0; mt < 2; mt++) {
        int r = m0 + wr * 32 + mt * 16 + (lane >> 2);
#pragma unroll
        for (int nt = 0; nt < 8; nt++) {
            int col = n0 + wc * 64 + nt * 8 + (lane & 3) * 2;
            float bx = 0.f, by = 0.f;
            if (bias) { bx = bias[col]; by = bias[col + 1]; }
            *(float2*)(C + (size_t)r * Nw + col) =
                make_float2(acc[mt][nt][0] + bx, acc[mt][nt][1] + by);
            *(float2*)(C + (size_t)(r + 8) * Nw + col) =
                make_float2(acc[mt][nt][2] + bx, acc[mt][nt][3] + by);
        }
    }
}

// ---------------- conversions ----------------
__global__ void __launch_bounds__(256) cvt_k(const float4* __restrict__ in,
                                             __nv_bfloat162* __restrict__ out)
{
    size_t i = (size_t)blockIdx.x * 256 + threadIdx.x;
    float4 v = in[i];
    out[2*i]   = __floats2bfloat162_rn(v.x, v.y);
    out[2*i+1] = __floats2bfloat162_rn(v.z, v.w);
}
__global__ void __launch_bounds__(256) cvt_split_k(const float4* __restrict__ in,
                                                   __nv_bfloat162* __restrict__ oh,
                                                   __nv_bfloat162* __restrict__ ol)
{
    size_t i = (size_t)blockIdx.x * 256 + threadIdx.x;
    float4 v = in[i];
    float f[4] = { v.x, v.y, v.z, v.w };
    __nv_bfloat16 h[4], l[4];
#pragma unroll
    for (int j = 0; j < 4; j++) {
        h[j] = __float2bfloat16(f[j]);
        l[j] = __float2bfloat16(f[j] - __bfloat162float(h[j]));
    }
    oh[2*i]   = __nv_bfloat162(h[0], h[1]);
    oh[2*i+1] = __nv_bfloat162(h[2], h[3]);
    ol[2*i]   = __nv_bfloat162(l[0], l[1]);
    ol[2*i+1] = __nv_bfloat162(l[2], l[3]);
}
__global__ void __launch_bounds__(256) cvtT_k(const float* __restrict__ in,
                                              __nv_bfloat16* __restrict__ out, int R, int Cc)
{
    __shared__ float tile[32][33];
    int cb = blockIdx.x * 32, rb = blockIdx.y * 32;
    int tx = threadIdx.x & 31, ty = threadIdx.x >> 5;
#pragma unroll
    for (int i = 0; i < 32; i += 8)
        tile[ty + i][tx] = in[(size_t)(rb + ty + i) * Cc + cb + tx];
    __syncthreads();
#pragma unroll
    for (int i = 0; i < 32; i += 8)
        out[(size_t)(cb + ty + i) * R + rb + tx] = __float2bfloat16(tile[tx][ty + i]);
}

// ---------------- fused row-l2norm ----------------
__global__ void __launch_bounds__(256) rownorm_split_k(const float* __restrict__ X,
                                                       __nv_bfloat16* __restrict__ oh,
                                                       __nv_bfloat16* __restrict__ ol)
{
    __shared__ float red[256];
    int r = blockIdx.x, t = threadIdx.x;
    float ss = 0.f;
    for (int c = t; c < DD; c += 256) { float v = X[(size_t)r * DD + c]; ss += v * v; }
    red[t] = ss; __syncthreads();
    for (int s = 128; s > 0; s >>= 1) { if (t < s) red[t] += red[t + s]; __syncthreads(); }
    float sc = 1.0f / fmaxf(sqrtf(red[0]), 1e-12f);
    for (int c = t; c < DD; c += 256) {
        float v = X[(size_t)r * DD + c] * sc;
        __nv_bfloat16 h = __float2bfloat16(v);
        oh[(size_t)r * DD + c] = h;
        ol[(size_t)r * DD + c] = __float2bfloat16(v - __bfloat162float(h));
    }
}
__global__ void __launch_bounds__(256) rownorm_bf_k(float* __restrict__ X,
                                                    __nv_bfloat16* __restrict__ ob)
{
    __shared__ float red[256];
    int r = blockIdx.x, t = threadIdx.x;
    float ss = 0.f;
    for (int c = t; c < DD; c += 256) { float v = X[(size_t)r * DD + c]; ss += v * v; }
    red[t] = ss; __syncthreads();
    for (int s = 128; s > 0; s >>= 1) { if (t < s) red[t] += red[t + s]; __syncthreads(); }
    float sc = 1.0f / fmaxf(sqrtf(red[0]), 1e-12f);
    for (int c = t; c < DD; c += 256) {
        float v = X[(size_t)r * DD + c] * sc;
        X[(size_t)r * DD + c] = v;
        ob[(size_t)r * DD + c] = __float2bfloat16(v);
    }
}

// ---------------- fused elementwise ----------------
__global__ void __launch_bounds__(256) silu_bf_k(const float4* __restrict__ h,
                                                 float4* __restrict__ a,
                                                 __nv_bfloat162* __restrict__ ab)
{
    size_t i = (size_t)blockIdx.x * 256 + threadIdx.x;
    float4 x = h[i], o;
    o.x = x.x / (1.0f + expf(-x.x)); o.y = x.y / (1.0f + expf(-x.y));
    o.z = x.z / (1.0f + expf(-x.z)); o.w = x.w / (1.0f + expf(-x.w));
    a[i] = o;
    ab[2*i]   = __floats2bfloat162_rn(o.x, o.y);
    ab[2*i+1] = __floats2bfloat162_rn(o.z, o.w);
}
__global__ void __launch_bounds__(256) silu_split_k(const float4* __restrict__ h,
                                                    __nv_bfloat162* __restrict__ oh,
                                                    __nv_bfloat162* __restrict__ ol)
{
    size_t i = (size_t)blockIdx.x * 256 + threadIdx.x;
    float4 x = h[i];
    float f[4] = { x.x / (1.0f + expf(-x.x)), x.y / (1.0f + expf(-x.y)),
                   x.z / (1.0f + expf(-x.z)), x.w / (1.0f + expf(-x.w)) };
    __nv_bfloat16 hh[4], ll[4];
#pragma unroll
    for (int j = 0; j < 4; j++) {
        hh[j] = __float2bfloat16(f[j]);
        ll[j] = __float2bfloat16(f[j] - __bfloat162float(hh[j]));
    }
    oh[2*i]   = __nv_bfloat162(hh[0], hh[1]);
    oh[2*i+1] = __nv_bfloat162(hh[2], hh[3]);
    ol[2*i]   = __nv_bfloat162(ll[0], ll[1]);
    ol[2*i+1] = __nv_bfloat162(ll[2], ll[3]);
}
__global__ void __launch_bounds__(256) make_dy_bf_k(const float4* __restrict__ v,
                                                    float4* __restrict__ y,
                                                    __nv_bfloat162* __restrict__ ob)
{
    size_t i = (size_t)blockIdx.x * 256 + threadIdx.x;
    const float sc = 2.0f / (float)SD;
    float4 yy = y[i], vv = v[i], o;
    o.x = (yy.x - vv.x) * sc; o.y = (yy.y - vv.y) * sc;
    o.z = (yy.z - vv.z) * sc; o.w = (yy.w - vv.w) * sc;
    y[i] = o;
    ob[2*i]   = __floats2bfloat162_rn(o.x, o.y);
    ob[2*i+1] = __floats2bfloat162_rn(o.z, o.w);
}
__global__ void __launch_bounds__(256) make_dh_k(const float4* __restrict__ h,
                                                 float4* __restrict__ dh)
{
    size_t i = (size_t)blockIdx.x * 256 + threadIdx.x;
    float4 x = h[i], d = dh[i];
    float f[4] = { x.x, x.y, x.z, x.w };
    float g[4] = { d.x, d.y, d.z, d.w };
#pragma unroll
    for (int j = 0; j < 4; j++) {
        float sg = 1.0f / (1.0f + expf(-f[j]));
        g[j] *= sg * (1.0f + f[j] * (1.0f - sg));
    }
    dh[i] = make_float4(g[0], g[1], g[2], g[3]);
}
__global__ void __launch_bounds__(256) colsum_k(const float* __restrict__ M, float* __restrict__ out)
{
    int c = blockIdx.x * 256 + threadIdx.x;
    float s0 = 0.f, s1 = 0.f, s2 = 0.f, s3 = 0.f;
    for (int r = 0; r < SS; r += 4) {
        s0 += M[(size_t)(r+0)*DD + c]; s1 += M[(size_t)(r+1)*DD + c];
        s2 += M[(size_t)(r+2)*DD + c]; s3 += M[(size_t)(r+3)*DD + c];
    }
    out[c] = (s0 + s1) + (s2 + s3);
}
__global__ void __launch_bounds__(256) alpha_partial_k(const float* __restrict__ x,
                                                       const float* __restrict__ aw,
                                                       float* __restrict__ part)
{
    __shared__ float red[256];
    int b = blockIdx.x, t = threadIdx.x;
    size_t base = (size_t)b * 8192;
    float s = 0.f;
    for (int i = t; i < 8192; i += 256) s += x[base + i] * aw[i & (DD - 1)];
    red[t] = s; __syncthreads();
    for (int k = 128; k > 0; k >>= 1) { if (t < k) red[t] += red[t + k]; __syncthreads(); }
    if (t == 0) part[b] = red[0];
}
__global__ void __launch_bounds__(256) alpha_final_k(const float* __restrict__ ab,
                                                     const float* __restrict__ part,
                                                     float* __restrict__ alpha)
{
    __shared__ float red[256];
    int t = threadIdx.x;
    float s = 0.f;
    for (int i = t; i < 2048; i += 256) s += part[i];
    red[t] = s; __syncthreads();
    for (int k = 128; k > 0; k >>= 1) { if (t < k) red[t] += red[t + k]; __syncthreads(); }
    if (t == 0) alpha[0] = 1.0f / (1.0f + expf(-(red[0] / (float)SS + ab[0])));
}
__global__ void __launch_bounds__(256) fastw_split_k(const float4* __restrict__ W,
                                                     const float4* __restrict__ Gm,
                                                     float4* __restrict__ Wf,
                                                     __nv_bfloat162* __restrict__ oh,
                                                     __nv_bfloat162* __restrict__ ol,
                                                     const float* __restrict__ alpha)
{
    size_t i = (size_t)blockIdx.x * 256 + threadIdx.x;
    float am1 = 1.0f - alpha[0];
    float4 w = W[i], g = Gm[i], o;
    o.x = am1 * w.x - INNER_LR * g.x; o.y = am1 * w.y - INNER_LR * g.y;
    o.z = am1 * w.z - INNER_LR * g.z; o.w = am1 * w.w - INNER_LR * g.w;
    Wf[i] = o;
    float f[4] = { o.x, o.y, o.z, o.w };
    __nv_bfloat16 hh[4], ll[4];
#pragma unroll
    for (int j = 0; j < 4; j++) {
        hh[j] = __float2bfloat16(f[j]);
        ll[j] = __float2bfloat16(f[j] - __bfloat162float(hh[j]));
    }
    oh[2*i]   = __nv_bfloat162(hh[0], hh[1]);
    oh[2*i+1] = __nv_bfloat162(hh[2], hh[3]);
    ol[2*i]   = __nv_bfloat162(ll[0], ll[1]);
    ol[2*i+1] = __nv_bfloat162(ll[2], ll[3]);
}
__global__ void __launch_bounds__(256) fastb_k(
    const float* __restrict__ b1, const float* __restrict__ gb1, float* __restrict__ b1f,
    const float* __restrict__ b2, const float* __restrict__ gb2, float* __restrict__ b2f,
    const float* __restrict__ alpha)
{
    int i = blockIdx.x * 256 + threadIdx.x;
    float am1 = 1.0f - alpha[0];
    b1f[i] = am1 * b1[i] - INNER_LR * gb1[i];
    b2f[i] = am1 * b2[i] - INNER_LR * gb2[i];
}

// ---------------- launch ----------------
extern "C" void kernel_launch(void* const* d_in, const int* in_sizes, int n_in,
                              void* d_out, int out_size)
{
    const float* x   = (const float*)d_in[0];
    const float* W_Q = (const float*)d_in[1];
    const float* W_K = (const float*)d_in[2];
    const float* W_V = (const float*)d_in[3];
    const float* aw  = (const float*)d_in[4];
    const float* ab  = (const float*)d_in[5];
    const float* W1  = (const float*)d_in[6];
    const float* b1  = (const float*)d_in[7];
    const float* W2  = (const float*)d_in[8];
    const float* b2  = (const float*)d_in[9];
    float* out = (float*)d_out;

    float* F; __nv_bfloat16* Bp;
    cudaGetSymbolAddress((void**)&F, g_f32);
    cudaGetSymbolAddress((void**)&Bp, g_bf);

    const int SMB = 3 * 49152;   // gemm_big: NS=3, 144KB
    const int SMS = 3 * 32768;   // gemm_split: NS=3, 96KB
    cudaFuncSetAttribute((const void*)gemm_big, cudaFuncAttributeMaxDynamicSharedMemorySize, SMB);
    cudaFuncSetAttribute((const void*)gemm_split, cudaFuncAttributeMaxDynamicSharedMemorySize, SMS);

    dim3 blk(256);
    dim3 gSDb(DD / 128, SS / 256);   // gemm_big: [S,D] outputs
    dim3 gDDb(DD / 128, DD / 256);   // gemm_big: [D,D] outputs
    dim3 gSDs(DD / 128, SS / 128);   // split
    int ew4 = SD / 1024, ewW4 = DD2 / 1024;
    dim3 tSD(DD / 32, SS / 32), tDD(DD / 32, DD / 32);

    // launches 0-4: conversions needed before first GEMM
    cvt_split_k<<<ew4, blk>>>((const float4*)x, (__nv_bfloat162*)(Bp+B_XH), (__nv_bfloat162*)(Bp+B_XL));
    cvt_split_k<<<ewW4, blk>>>((const float4*)W_Q, (__nv_bfloat162*)(Bp+B_WQH), (__nv_bfloat162*)(Bp+B_WQL));
    cvt_k<<<ewW4, blk>>>((const float4*)W_K, (__nv_bfloat162*)(Bp+B_WK));
    cvt_k<<<ewW4, blk>>>((const float4*)W_V, (__nv_bfloat162*)(Bp+B_WV));
    cvt_k<<<ewW4, blk>>>((const float4*)W1, (__nv_bfloat162*)(Bp+B_W1));

    // launch 5: gemm_big (profiled by ncu -s 5 -c 1)
    gemm_big<<<gSDb, blk, SMB>>>(Bp+B_XH, Bp+B_WK, F+F_K, nullptr, DD, DD);

    // remaining conversions + alpha
    cvt_k<<<ewW4, blk>>>((const float4*)W2, (__nv_bfloat162*)(Bp+B_W2));
    cvtT_k<<<tDD, blk>>>(W2, Bp + B_W2T, DD, DD);
    alpha_partial_k<<<2048, blk>>>(x, aw, F + F_PART);
    alpha_final_k<<<1, blk>>>(ab, F + F_PART, F + F_ALPHA);

    // q (split), v
    gemm_split<<<gSDs, blk, SMS>>>(Bp+B_XH, Bp+B_XL, Bp+B_WQH, Bp+B_WQL, F+F_Q, nullptr, DD, DD);
    gemm_big<<<gSDb, blk, SMB>>>(Bp+B_XH, Bp+B_WV, F+F_V, nullptr, DD, DD);
    rownorm_split_k<<<SS, blk>>>(F + F_Q, Bp + B_QH, Bp + B_QL);
    rownorm_bf_k<<<SS, blk>>>(F + F_K, Bp + B_K);
    cvtT_k<<<tSD, blk>>>(F + F_K, Bp + B_KT, SS, DD);

    // forward MLP on k
    gemm_big<<<gSDb, blk, SMB>>>(Bp+B_K, Bp+B_W1, F+F_H, b1, DD, DD);
    silu_bf_k<<<ew4, blk>>>((const float4*)(F+F_H), (float4*)(F+F_A), (__nv_bfloat162*)(Bp+B_A));
    cvtT_k<<<tSD, blk>>>(F + F_A, Bp + B_AT, SS, DD);
    gemm_big<<<gSDb, blk, SMB>>>(Bp+B_A, Bp+B_W2, F+F_DY, b2, DD, DD);
    make_dy_bf_k<<<ew4, blk>>>((const float4*)(F+F_V), (float4*)(F+F_DY), (__nv_bfloat162*)(Bp+B_DY));
    cvtT_k<<<tSD, blk>>>(F + F_DY, Bp + B_DYT, SS, DD);

    // gW2 = dy^T @ a ; gb2
    gemm_big<<<gDDb, blk, SMB>>>(Bp+B_DYT, Bp+B_AT, F+F_GW2, nullptr, DD, SS);
    colsum_k<<<DD / 256, blk>>>(F + F_DY, F + F_GB2);

    // dh = (dy @ W2) * dsilu(h) ; gW1 = dh^T @ k ; gb1
    gemm_big<<<gSDb, blk, SMB>>>(Bp+B_DY, Bp+B_W2T, F+F_DH, nullptr, DD, DD);
    make_dh_k<<<ew4, blk>>>((const float4*)(F+F_H), (float4*)(F+F_DH));
    cvtT_k<<<tSD, blk>>>(F + F_DH, Bp + B_DHT, SS, DD);
    gemm_big<<<gDDb, blk, SMB>>>(Bp+B_DHT, Bp+B_KT, F+F_GW1, nullptr, DD, SS);
    colsum_k<<<DD / 256, blk>>>(F + F_DH, F + F_GB1);

    // fast weights (+ fused split conversion)
    fastw_split_k<<<ewW4, blk>>>((const float4*)W1, (const float4*)(F+F_GW1), (float4*)(F+F_W1F),
                                 (__nv_bfloat162*)(Bp+B_W1FH), (__nv_bfloat162*)(Bp+B_W1FL), F+F_ALPHA);
    fastw_split_k<<<ewW4, blk>>>((const float4*)W2, (const float4*)(F+F_GW2), (float4*)(F+F_W2F),
                                 (__nv_bfloat162*)(Bp+B_W2FH), (__nv_bfloat162*)(Bp+B_W2FL), F+F_ALPHA);
    fastb_k<<<DD / 256, blk>>>(b1, F+F_GB1, F+F_B1F, b2, F+F_GB2, F+F_B2F, F+F_ALPHA);

    // retrieve (split precision)
    gemm_split<<<gSDs, blk, SMS>>>(Bp+B_QH, Bp+B_QL, Bp+B_W1FH, Bp+B_W1FL, F+F_H, F+F_B1F, DD, DD);
    silu_split_k<<<ew4, blk>>>((const float4*)(F+F_H), (__nv_bfloat162*)(Bp+B_ARH), (__nv_bfloat162*)(Bp+B_ARL));
    gemm_split<<<gSDs, blk, SMS>>>(Bp+B_ARH, Bp+B_ARL, Bp+B_W2FH, Bp+B_W2FL, out, F+F_B2F, DD, DD);
}